// round 15
// baseline (speedup 1.0000x reference)
#include <cuda_runtime.h>
#include <cuda_bf16.h>
#include <cstdint>
#include <math_constants.h>

#define B_ 64
#define L_ 1024
#define P_ 2047
#define NS 16
#define SBI 272
#define TI  (64 * SBI)
#define GS  68
#define GSZ (64 * GS)

#define O_K  0
#define O_P  TI
#define O_V  (2 * TI)
#define O_PP (3 * TI)           // p (probability-numerator) tile
#define O_G  (4 * TI)           // ring (2 slots) / stats / cnt overlay
#define SMEMB (4 * TI + 2 * GSZ * 4)   // 104448 -> 2 CTAs/SM

__device__ float g_S[B_ * L_];

__device__ __forceinline__ uint32_t smem_u32(const void* p) {
    uint32_t a;
    asm("{ .reg .u64 t; cvta.to.shared.u64 t, %1; cvt.u32.u64 %0, t; }" : "=r"(a) : "l"(p));
    return a;
}
#define LDSM4(r, a) \
    asm volatile("ldmatrix.sync.aligned.m8n8.x4.shared.b16 {%0,%1,%2,%3}, [%4];" \
        : "=r"((r)[0]), "=r"((r)[1]), "=r"((r)[2]), "=r"((r)[3]) : "r"(a))
#define LDSM4T(r, a) \
    asm volatile("ldmatrix.sync.aligned.m8n8.x4.trans.shared.b16 {%0,%1,%2,%3}, [%4];" \
        : "=r"((r)[0]), "=r"((r)[1]), "=r"((r)[2]), "=r"((r)[3]) : "r"(a))
#define MMA(c, a, b) \
    asm volatile("mma.sync.aligned.m16n8k16.row.col.f32.bf16.bf16.f32 " \
        "{%0,%1,%2,%3}, {%4,%5,%6,%7}, {%8,%9}, {%0,%1,%2,%3};" \
        : "+f"((c)[0]), "+f"((c)[1]), "+f"((c)[2]), "+f"((c)[3]) \
        : "r"((a)[0]), "r"((a)[1]), "r"((a)[2]), "r"((a)[3]), "r"((b)[0]), "r"((b)[1]))

__device__ __forceinline__ uint32_t pk2(float a, float b) {
    return (uint32_t)__bfloat16_as_ushort(__float2bfloat16(a)) |
           ((uint32_t)__bfloat16_as_ushort(__float2bfloat16(b)) << 16);
}
__device__ __forceinline__ float bfres(float x) {
    return x - __bfloat162float(__float2bfloat16(x));
}
__device__ __forceinline__ void st_blk(char* sm, int oT, int r, int bl, float4 a, float4 b) {
    uint4 hi = make_uint4(pk2(a.x, a.y), pk2(a.z, a.w), pk2(b.x, b.y), pk2(b.z, b.w));
    uint4 lo = make_uint4(pk2(bfres(a.x), bfres(a.y)), pk2(bfres(a.z), bfres(a.w)),
                          pk2(bfres(b.x), bfres(b.y)), pk2(bfres(b.z), bfres(b.w)));
    char* p = sm + oT + r * SBI + bl * 32;
    *(uint4*)p = hi;
    *(uint4*)(p + 16) = lo;
}

__global__ __launch_bounds__(256, 2)
void fused_bal_kernel(const float* __restrict__ q, const float* __restrict__ kk,
                      const float* __restrict__ v, const float* __restrict__ pos,
                      const char* __restrict__ maskp, float* __restrict__ out,
                      float* __restrict__ attn) {
    extern __shared__ char sm[];
    const uint32_t sb = smem_u32(sm);
    const int tid = threadIdx.x;
    const int lane = tid & 31, w = tid >> 5;
    const bool isS = (w < 4);
    const int wr = w & 3;
    const int b = blockIdx.y, l0 = blockIdx.x * 64;

    const float* qb = q + (size_t)b * L_ * 64;
    const float* kb = kk + (size_t)b * L_ * 64;
    const float* vb = v + (size_t)b * L_ * 64;
    const float* pb = pos + (size_t)b * P_ * 64;

    float* ring = (float*)(sm + O_G);
    int* cnt = (int*)(sm + O_G);

    // ---- mask dtype detection ----
    if (tid < 2) cnt[tid] = 0;
    __syncthreads();
    {
        int c0 = 0, c1 = 0;
        #pragma unroll
        for (int e = 0; e < 2; e++) {
            uint4 u = ((const uint4*)maskp)[tid * 2 + e];
            uint32_t ws[4] = {u.x, u.y, u.z, u.w};
            #pragma unroll
            for (int wd = 0; wd < 4; wd++) {
                c0 += ((ws[wd] & 0x000000ffu) != 0);
                c1 += ((ws[wd] & 0x0000ff00u) != 0);
            }
        }
        if (c0) atomicAdd(&cnt[0], c0);
        if (c1) atomicAdd(&cnt[1], c1);
    }

    auto fill_K = [&](int t) {
        #pragma unroll
        for (int e = 0; e < 2; e++) {
            int tt = tid + e * 256, r = tt & 63, bl = tt >> 6;
            const float* ap = kb + (size_t)(t * 64 + r) * 64 + bl * 8;
            st_blk(sm, O_K, r, bl, *(const float4*)ap, *(const float4*)(ap + 4));
        }
    };
    auto fill_V = [&](int t) {
        #pragma unroll
        for (int e = 0; e < 2; e++) {
            int tt = tid + e * 256, r = tt & 63, bl = tt >> 6;
            const float* ap = vb + (size_t)(t * 64 + r) * 64 + bl * 8;
            st_blk(sm, O_V, r, bl, *(const float4*)ap, *(const float4*)(ap + 4));
        }
    };
    auto fill_P = [&](int win) {
        #pragma unroll
        for (int e = 0; e < 2; e++) {
            int tt = tid + e * 256, r = tt & 63, bl = tt >> 6;
            int pr = l0 + 64 * win + r; if (pr > P_ - 1) pr = P_ - 1;
            const float* ap = pb + (size_t)pr * 64 + bl * 8;
            st_blk(sm, O_P, r, bl, *(const float4*)ap, *(const float4*)(ap + 4));
        }
    };

    // prologue: Q -> K slot, R -> P slot (scaled 1/8)
    #pragma unroll
    for (int e = 0; e < 2; e++) {
        int tt = tid + e * 256, r = tt & 63, bl = tt >> 6;
        const float* ap = qb + (size_t)(l0 + r) * 64 + bl * 8;
        float4 a0 = *(const float4*)ap, a1 = *(const float4*)(ap + 4);
        a0.x *= .125f; a0.y *= .125f; a0.z *= .125f; a0.w *= .125f;
        a1.x *= .125f; a1.y *= .125f; a1.z *= .125f; a1.w *= .125f;
        st_blk(sm, O_K, r, bl, a0, a1);
        const float* rp = qb + (size_t)(L_ - 1 - (l0 + r)) * 64 + bl * 8;
        float4 r0v = *(const float4*)rp, r1v = *(const float4*)(rp + 4);
        r0v.x *= .125f; r0v.y *= .125f; r0v.z *= .125f; r0v.w *= .125f;
        r1v.x *= .125f; r1v.y *= .125f; r1v.z *= .125f; r1v.w *= .125f;
        st_blk(sm, O_P, r, bl, r0v, r1v);
    }
    __syncthreads();
    const int mode = (cnt[0] > 0 && cnt[1] > 0) ? 0 : 1;

    auto adA = [&](int oT, int kc, int hi) -> uint32_t {
        int row = 16 * wr + (lane & 15), blk = 2 * kc + (lane >> 4);
        return sb + oT + row * SBI + blk * 32 + (hi ? 0 : 16);
    };
    auto adB = [&](int oT, int np, int kc, int hi) -> uint32_t {
        int nrow = 16 * np + 8 * (lane >> 4) + (lane & 7);
        int blk = 2 * kc + ((lane >> 3) & 1);
        return sb + oT + nrow * SBI + blk * 32 + (hi ? 0 : 16);
    };
    auto adBT = [&](int oT, int np, int kc, int hi) -> uint32_t {
        int krow = 16 * kc + (lane & 15);
        int blk = 2 * np + (lane >> 4);
        return sb + oT + krow * SBI + blk * 32 + (hi ? 0 : 16);
    };
    const int r0 = 16 * wr + (lane >> 2), c2 = lane & 3;

    // cache A fragments: S warps Q (K slot), G warps R (P slot)
    uint32_t Ah[4][4], Al[4][4];
    {
        int oT = isS ? O_K : O_P;
        #pragma unroll
        for (int kc = 0; kc < 4; kc++) { LDSM4(Ah[kc], adA(oT, kc, 1)); LDSM4(Al[kc], adA(oT, kc, 0)); }
    }
    __syncthreads();
    fill_K(0); fill_P(0);
    __syncthreads();

    float accA[8][4];
    float accO[4][4] = {};
    float run_s[2] = {0.f, 0.f};

    auto gemm64 = [&](int oB, float acc[8][4]) {
        #pragma unroll
        for (int kc = 0; kc < 4; kc++)
            #pragma unroll
            for (int np = 0; np < 4; np++) {
                uint32_t bh[4], bl_[4];
                LDSM4(bh, adB(oB, np, kc, 1));
                MMA(acc[2 * np], Ah[kc], bh);     MMA(acc[2 * np], Al[kc], bh);
                MMA(acc[2 * np + 1], Ah[kc], bh + 2); MMA(acc[2 * np + 1], Al[kc], bh + 2);
                LDSM4(bl_, adB(oB, np, kc, 0));
                MMA(acc[2 * np], Ah[kc], bl_);    MMA(acc[2 * np + 1], Ah[kc], bl_ + 2);
            }
    };
    // PV n-half from smem p (G warps): np base 2
    auto pv_smem = [&]() {
        #pragma unroll
        for (int kc = 0; kc < 4; kc++) {
            uint32_t Ph[4], Pl[4];
            LDSM4(Ph, adA(O_PP, kc, 1));
            LDSM4(Pl, adA(O_PP, kc, 0));
            #pragma unroll
            for (int np = 0; np < 2; np++) {
                uint32_t bh[4], bl_[4];
                LDSM4T(bh, adBT(O_V, np + 2, kc, 1));
                MMA(accO[2 * np], Ph, bh);     MMA(accO[2 * np], Pl, bh);
                MMA(accO[2 * np + 1], Ph, bh + 2); MMA(accO[2 * np + 1], Pl, bh + 2);
                LDSM4T(bl_, adBT(O_V, np + 2, kc, 0));
                MMA(accO[2 * np], Ph, bl_);    MMA(accO[2 * np + 1], Ph, bl_ + 2);
            }
        }
    };
    auto ring_store = [&](int slot) {
        float* gn = ring + slot * GSZ;
        #pragma unroll
        for (int nf = 0; nf < 8; nf++) {
            int j0 = 8 * nf + 2 * c2;
            #pragma unroll
            for (int h = 0; h < 2; h++) {
                int i = r0 + 8 * h;
                *(float2*)(gn + i * GS + j0) = make_float2(accA[nf][2 * h], accA[nf][2 * h + 1]);
            }
        }
    };

    // prologue G(0)
    if (!isS) {
        #pragma unroll
        for (int nf = 0; nf < 8; nf++)
            #pragma unroll
            for (int e = 0; e < 4; e++) accA[nf][e] = 0.f;
        gemm64(O_P, accA);
    }
    __syncthreads();
    if (!isS) ring_store(0);
    fill_P(1);
    __syncthreads();

    // ================= main loop =================
    for (int t = 0; t < NS; t++) {
        #pragma unroll
        for (int nf = 0; nf < 8; nf++)
            #pragma unroll
            for (int e = 0; e < 4; e++) accA[nf][e] = 0.f;
        if (isS) {
            gemm64(O_K, accA);                  // S(t)
        } else {
            if (t > 0) pv_smem();               // PV(t-1), n-hi
            gemm64(O_P, accA);                  // G(t+1)
        }
        __syncthreads();                        // BAR1
        if (!isS) ring_store((t + 1) & 1);
        if (t < NS - 1) fill_K(t + 1);
        fill_P(t + 2);
        fill_V(t);
        __syncthreads();                        // BAR2
        if (isS) {
            // epilogue: bias + mask + logit store + exp; p -> smem + register frags
            const float* gc = ring + (t & 1) * GSZ;
            const float* gn = ring + ((t + 1) & 1) * GSZ;
            uint32_t Ph[4][4], Pl[4][4];
            #pragma unroll
            for (int nf = 0; nf < 8; nf++) {
                int j0 = 8 * nf + 2 * c2;
                int kc = nf >> 1;
                #pragma unroll
                for (int h = 0; h < 2; h++) {
                    int i = r0 + 8 * h;
                    int s0 = i + j0, s1 = s0 + 1;
                    float x0 = accA[nf][2 * h] + ((s0 < 64) ? gc : gn)[i * GS + (s0 & 63)];
                    float x1 = accA[nf][2 * h + 1] + ((s1 < 64) ? gc : gn)[i * GS + (s1 & 63)];
                    size_t gidx = ((size_t)b * L_ + l0 + i) * L_ + t * 64 + j0;
                    if (mode == 0) {
                        unsigned short mv = *(const unsigned short*)(maskp + gidx);
                        if (mv & 0x00ff) x0 = -CUDART_INF_F;
                        if (mv & 0xff00) x1 = -CUDART_INF_F;
                    } else {
                        uint2 mv = *(const uint2*)((const uint32_t*)maskp + gidx);
                        if (mv.x) x0 = -CUDART_INF_F;
                        if (mv.y) x1 = -CUDART_INF_F;
                    }
                    *(float2*)(attn + gidx) = make_float2(x0, x1);
                    float e0 = __expf(x0), e1 = __expf(x1);
                    run_s[h] += e0 + e1;
                    int reg = 2 * (nf & 1) + h;
                    uint32_t ph = pk2(e0, e1), pl = pk2(bfres(e0), bfres(e1));
                    Ph[kc][reg] = ph; Pl[kc][reg] = pl;
                    char* pp = sm + O_PP + i * SBI + nf * 32 + c2 * 4;
                    *(uint32_t*)pp = ph;
                    *(uint32_t*)(pp + 16) = pl;
                }
            }
            // PV(t) n-lo from register p
            #pragma unroll
            for (int kc = 0; kc < 4; kc++)
                #pragma unroll
                for (int np = 0; np < 2; np++) {
                    uint32_t bh[4], bl_[4];
                    LDSM4T(bh, adBT(O_V, np, kc, 1));
                    MMA(accO[2 * np], Ph[kc], bh);     MMA(accO[2 * np], Pl[kc], bh);
                    MMA(accO[2 * np + 1], Ph[kc], bh + 2); MMA(accO[2 * np + 1], Pl[kc], bh + 2);
                    LDSM4T(bl_, adBT(O_V, np, kc, 0));
                    MMA(accO[2 * np], Ph[kc], bl_);    MMA(accO[2 * np + 1], Ph[kc], bl_ + 2);
                }
        }
        __syncthreads();                        // BAR3
    }

    // ================= finale =================
    float* stats = ring;                        // ring dead now
    if (isS) {
        #pragma unroll
        for (int h = 0; h < 2; h++) {
            float s = run_s[h];
            s += __shfl_xor_sync(0xffffffffu, s, 1);
            s += __shfl_xor_sync(0xffffffffu, s, 2);
            run_s[h] = s;
            if (c2 == 0) {
                stats[r0 + 8 * h] = s;
                g_S[(size_t)b * L_ + l0 + r0 + 8 * h] = s;
            }
        }
    } else {
        pv_smem();                              // PV(15), n-hi
    }
    __syncthreads();
    if (isS) {
        #pragma unroll
        for (int g = 0; g < 4; g++) {
            int j0 = 8 * g + 2 * c2;
            #pragma unroll
            for (int h = 0; h < 2; h++) {
                float invS = 1.f / run_s[h];
                int i = r0 + 8 * h;
                *(float2*)(out + ((size_t)b * L_ + l0 + i) * 64 + j0) =
                    make_float2(accO[g][2 * h] * invS, accO[g][2 * h + 1] * invS);
            }
        }
    } else {
        #pragma unroll
        for (int g = 0; g < 4; g++) {
            int j0 = 32 + 8 * g + 2 * c2;
            #pragma unroll
            for (int h = 0; h < 2; h++) {
                int i = r0 + 8 * h;
                float invS = 1.f / stats[i];
                *(float2*)(out + ((size_t)b * L_ + l0 + i) * 64 + j0) =
                    make_float2(accO[g][2 * h] * invS, accO[g][2 * h + 1] * invS);
            }
        }
    }
}

__global__ __launch_bounds__(256)
void norm_kernel(float* __restrict__ attn) {
    int gid = blockIdx.x * 256 + threadIdx.x;
    int row = gid >> 6;
    int seg = gid & 63;
    float invS = 1.f / g_S[row];
    float* p = attn + (size_t)row * L_ + seg * 16;
    #pragma unroll
    for (int e = 0; e < 4; e++) {
        float4 x = *(float4*)(p + 4 * e);
        x.x = __expf(x.x) * invS; x.y = __expf(x.y) * invS;
        x.z = __expf(x.z) * invS; x.w = __expf(x.w) * invS;
        *(float4*)(p + 4 * e) = x;
    }
}

extern "C" void kernel_launch(void* const* d_in, const int* in_sizes, int n_in,
                              void* d_out, int out_size) {
    const float* q = (const float*)d_in[0];
    const float* k = (const float*)d_in[1];
    const float* v = (const float*)d_in[2];
    const float* pos = (const float*)d_in[3];
    const char* msk = (const char*)d_in[4];
    float* out = (float*)d_out;
    float* attn = out + (size_t)B_ * L_ * 64;

    cudaFuncSetAttribute(fused_bal_kernel,
                         cudaFuncAttributeMaxDynamicSharedMemorySize, SMEMB);
    fused_bal_kernel<<<dim3(16, B_), 256, SMEMB>>>(q, k, v, pos, msk, out, attn);
    norm_kernel<<<(B_ * L_ * L_) / (256 * 16), 256>>>(attn);
}

// round 16
// speedup vs baseline: 1.1183x; 1.1183x over previous
#include <cuda_runtime.h>
#include <cuda_bf16.h>
#include <cstdint>
#include <math_constants.h>

#define B_ 64
#define L_ 1024
#define P_ 2047
#define NS 16
#define SBI 272                 // interleaved tile row stride (bytes)
#define TI  (64 * SBI)          // 17408 B per 64-row tile
#define GS  72                  // ring row stride (floats)
#define GSZ (64 * GS)
#define XST 68                  // x-exchange buffer row stride (floats)

#define O_Q  0                  // Q tile during prologue; x-exchange buffer after
#define O_R  TI
#define O_K  (2 * TI)           // K tile; V tile in phase 2
#define O_P  (3 * TI)           // pos tile; p tile in phase 2
#define O_G  (4 * TI)           // ring, 2 slots
#define O_ST (O_G + 2 * GSZ * 4)  // stats: 256 floats
#define O_MC (O_ST + 256 * 4)
#define SMEMB (O_MC + 16)

__device__ __forceinline__ uint32_t smem_u32(const void* p) {
    uint32_t a;
    asm("{ .reg .u64 t; cvta.to.shared.u64 t, %1; cvt.u32.u64 %0, t; }" : "=r"(a) : "l"(p));
    return a;
}
#define LDSM4(r, a) \
    asm volatile("ldmatrix.sync.aligned.m8n8.x4.shared.b16 {%0,%1,%2,%3}, [%4];" \
        : "=r"((r)[0]), "=r"((r)[1]), "=r"((r)[2]), "=r"((r)[3]) : "r"(a))
#define LDSM4T(r, a) \
    asm volatile("ldmatrix.sync.aligned.m8n8.x4.trans.shared.b16 {%0,%1,%2,%3}, [%4];" \
        : "=r"((r)[0]), "=r"((r)[1]), "=r"((r)[2]), "=r"((r)[3]) : "r"(a))
#define MMA(c, a, b) \
    asm volatile("mma.sync.aligned.m16n8k16.row.col.f32.bf16.bf16.f32 " \
        "{%0,%1,%2,%3}, {%4,%5,%6,%7}, {%8,%9}, {%0,%1,%2,%3};" \
        : "+f"((c)[0]), "+f"((c)[1]), "+f"((c)[2]), "+f"((c)[3]) \
        : "r"((a)[0]), "r"((a)[1]), "r"((a)[2]), "r"((a)[3]), "r"((b)[0]), "r"((b)[1]))

__device__ __forceinline__ uint32_t pk2(float a, float b) {
    return (uint32_t)__bfloat16_as_ushort(__float2bfloat16(a)) |
           ((uint32_t)__bfloat16_as_ushort(__float2bfloat16(b)) << 16);
}
__device__ __forceinline__ float bfres(float x) {
    return x - __bfloat162float(__float2bfloat16(x));
}
__device__ __forceinline__ void st_blk(char* sm, int oT, int r, int bl, float4 a, float4 b) {
    uint4 hi = make_uint4(pk2(a.x, a.y), pk2(a.z, a.w), pk2(b.x, b.y), pk2(b.z, b.w));
    uint4 lo = make_uint4(pk2(bfres(a.x), bfres(a.y)), pk2(bfres(a.z), bfres(a.w)),
                          pk2(bfres(b.x), bfres(b.y)), pk2(bfres(b.z), bfres(b.w)));
    char* p = sm + oT + r * SBI + bl * 32;
    *(uint4*)p = hi;
    *(uint4*)(p + 16) = lo;
}

__global__ __launch_bounds__(256, 2)
void fused_mma_kernel(const float* __restrict__ q, const float* __restrict__ kk,
                      const float* __restrict__ v, const float* __restrict__ pos,
                      const char* __restrict__ maskp, float* __restrict__ out,
                      float* __restrict__ attn) {
    extern __shared__ char sm[];
    const uint32_t sb = smem_u32(sm);
    const int tid = threadIdx.x;
    const int lane = tid & 31, w = tid >> 5;
    const int wr = w & 3, wc = w >> 2;       // 4 warps in m, 2 in n
    const int b = blockIdx.y, l0 = blockIdx.x * 64;

    const float* qb = q + (size_t)b * L_ * 64;
    const float* kb = kk + (size_t)b * L_ * 64;
    const float* vb = v + (size_t)b * L_ * 64;
    const float* pb = pos + (size_t)b * P_ * 64;

    float* ring = (float*)(sm + O_G);
    float* xbuf = (float*)(sm + O_Q);
    float* stp  = (float*)(sm + O_ST);
    int* cnt = (int*)(sm + O_MC);

    // ---- mask dtype detection (first 8KB) ----
    if (tid < 2) cnt[tid] = 0;
    __syncthreads();
    {
        int c0 = 0, c1 = 0;
        #pragma unroll
        for (int e = 0; e < 2; e++) {
            uint4 u = ((const uint4*)maskp)[tid * 2 + e];
            uint32_t ws[4] = {u.x, u.y, u.z, u.w};
            #pragma unroll
            for (int wd = 0; wd < 4; wd++) {
                c0 += ((ws[wd] & 0x000000ffu) != 0);
                c1 += ((ws[wd] & 0x0000ff00u) != 0);
            }
        }
        if (c0) atomicAdd(&cnt[0], c0);
        if (c1) atomicAdd(&cnt[1], c1);
    }

    // ---- tile fills ----
    auto fill_K = [&](int t) {
        #pragma unroll
        for (int e = 0; e < 2; e++) {
            int tt = tid + e * 256, r = tt & 63, bl = tt >> 6;
            const float* ap = kb + (size_t)(t * 64 + r) * 64 + bl * 8;
            st_blk(sm, O_K, r, bl, *(const float4*)ap, *(const float4*)(ap + 4));
        }
    };
    auto fill_V = [&](int t) {
        #pragma unroll
        for (int e = 0; e < 2; e++) {
            int tt = tid + e * 256, r = tt & 63, bl = tt >> 6;
            const float* ap = vb + (size_t)(t * 64 + r) * 64 + bl * 8;
            st_blk(sm, O_K, r, bl, *(const float4*)ap, *(const float4*)(ap + 4));
        }
    };
    auto fill_P = [&](int win) {
        #pragma unroll
        for (int e = 0; e < 2; e++) {
            int tt = tid + e * 256, r = tt & 63, bl = tt >> 6;
            int pr = l0 + 64 * win + r; if (pr > P_ - 1) pr = P_ - 1;
            const float* ap = pb + (size_t)pr * 64 + bl * 8;
            st_blk(sm, O_P, r, bl, *(const float4*)ap, *(const float4*)(ap + 4));
        }
    };

    // prologue: Q -> O_Q, R -> O_R (scaled 1/8), K0, P win0
    #pragma unroll
    for (int e = 0; e < 2; e++) {
        int tt = tid + e * 256, r = tt & 63, bl = tt >> 6;
        const float* ap = qb + (size_t)(l0 + r) * 64 + bl * 8;
        float4 a0 = *(const float4*)ap, a1 = *(const float4*)(ap + 4);
        a0.x *= .125f; a0.y *= .125f; a0.z *= .125f; a0.w *= .125f;
        a1.x *= .125f; a1.y *= .125f; a1.z *= .125f; a1.w *= .125f;
        st_blk(sm, O_Q, r, bl, a0, a1);
        const float* rp = qb + (size_t)(L_ - 1 - (l0 + r)) * 64 + bl * 8;
        float4 r0v = *(const float4*)rp, r1v = *(const float4*)(rp + 4);
        r0v.x *= .125f; r0v.y *= .125f; r0v.z *= .125f; r0v.w *= .125f;
        r1v.x *= .125f; r1v.y *= .125f; r1v.z *= .125f; r1v.w *= .125f;
        st_blk(sm, O_R, r, bl, r0v, r1v);
    }
    fill_K(0); fill_P(0);
    __syncthreads();
    const int mode = (cnt[0] > 0 && cnt[1] > 0) ? 0 : 1;

    auto adA = [&](int oT, int kc, int hi) -> uint32_t {
        int row = 16 * wr + (lane & 15), blk = 2 * kc + (lane >> 4);
        return sb + oT + row * SBI + blk * 32 + (hi ? 0 : 16);
    };
    auto adB = [&](int oT, int np, int kc, int hi) -> uint32_t {
        int nrow = 32 * wc + 16 * np + 8 * (lane >> 4) + (lane & 7);
        int blk = 2 * kc + ((lane >> 3) & 1);
        return sb + oT + nrow * SBI + blk * 32 + (hi ? 0 : 16);
    };
    auto adBT = [&](int oT, int np, int kc2, int hi) -> uint32_t {
        int krow = 32 * wc + 16 * kc2 + (lane & 15);
        int blk = 2 * np + (lane >> 4);
        return sb + oT + krow * SBI + blk * 32 + (hi ? 0 : 16);
    };

    const int r0 = 16 * wr + (lane >> 2), c2 = lane & 3;
    const int rr = tid >> 2, qq = tid & 3;     // row-domain mapping

    // persistent fragments: Q hi+lo, R hi (O_Q slot becomes xbuf after this)
    uint32_t Qh[4][4], Ql[4][4], Rh[4][4];
    #pragma unroll
    for (int kc = 0; kc < 4; kc++) {
        LDSM4(Qh[kc], adA(O_Q, kc, 1));
        LDSM4(Ql[kc], adA(O_Q, kc, 0));
        LDSM4(Rh[kc], adA(O_R, kc, 1));
    }

    auto gemm_S = [&](float acc[4][4]) {
        #pragma unroll
        for (int kc = 0; kc < 4; kc++)
            #pragma unroll
            for (int np = 0; np < 2; np++) {
                uint32_t bh[4], bl_[4];
                LDSM4(bh, adB(O_K, np, kc, 1));
                MMA(acc[2 * np], Qh[kc], bh);     MMA(acc[2 * np], Ql[kc], bh);
                MMA(acc[2 * np + 1], Qh[kc], bh + 2); MMA(acc[2 * np + 1], Ql[kc], bh + 2);
                LDSM4(bl_, adB(O_K, np, kc, 0));
                MMA(acc[2 * np], Qh[kc], bl_);    MMA(acc[2 * np + 1], Qh[kc], bl_ + 2);
            }
    };
    auto gemm_G = [&](float acc[4][4]) {
        #pragma unroll
        for (int kc = 0; kc < 4; kc++) {
            uint32_t rl[4];
            LDSM4(rl, adA(O_R, kc, 0));
            #pragma unroll
            for (int np = 0; np < 2; np++) {
                uint32_t bh[4], bl_[4];
                LDSM4(bh, adB(O_P, np, kc, 1));
                MMA(acc[2 * np], Rh[kc], bh);     MMA(acc[2 * np], rl, bh);
                MMA(acc[2 * np + 1], Rh[kc], bh + 2); MMA(acc[2 * np + 1], rl, bh + 2);
                LDSM4(bl_, adB(O_P, np, kc, 0));
                MMA(acc[2 * np], Rh[kc], bl_);    MMA(acc[2 * np + 1], Rh[kc], bl_ + 2);
            }
        }
    };
    auto ring_store = [&](float acc[4][4], int slot) {
        float* gn = ring + slot * GSZ;
        #pragma unroll
        for (int nf = 0; nf < 4; nf++) {
            int j0 = 32 * wc + 8 * nf + 2 * c2;
            #pragma unroll
            for (int h = 0; h < 2; h++) {
                int i = r0 + 8 * h;
                *(float2*)(gn + i * GS + j0) = make_float2(acc[nf][2 * h], acc[nf][2 * h + 1]);
            }
        }
    };

    // ---- prologue G0 ----
    {
        float accG[4][4] = {};
        gemm_G(accG);
        __syncthreads();
        ring_store(accG, 0);
        fill_P(1);
        __syncthreads();
    }

    float run_s = 0.f;     // per-(row,quarter) partial sum; no max needed

    // ================= phase 1 =================
    for (int t = 0; t < NS; t++) {
        float accS[4][4] = {};
        float accG[4][4] = {};
        gemm_S(accS);
        gemm_G(accG);
        __syncthreads();                           // BAR1: K/P/ring consumed
        ring_store(accG, (t + 1) & 1);
        if (t < NS - 1) fill_K(t + 1);
        fill_P(t + 2);
        __syncthreads();                           // BAR2: ring t+1 + tiles visible
        // fragment domain: bias add -> x into xbuf (conflict-free STS.64)
        const float* gc = ring + (t & 1) * GSZ;
        const float* gn = ring + ((t + 1) & 1) * GSZ;
        #pragma unroll
        for (int nf = 0; nf < 4; nf++) {
            int j0 = 32 * wc + 8 * nf + 2 * c2;
            #pragma unroll
            for (int h = 0; h < 2; h++) {
                int i = r0 + 8 * h;
                int s0 = i + j0, s1 = s0 + 1;
                float x0 = accS[nf][2 * h] + ((s0 < 64) ? gc : gn)[i * GS + (s0 & 63)];
                float x1 = accS[nf][2 * h + 1] + ((s1 < 64) ? gc : gn)[i * GS + (s1 & 63)];
                *(float2*)(xbuf + i * XST + j0) = make_float2(x0, x1);
            }
        }
        __syncthreads();                           // BAR3: xbuf complete
        // row domain: coalesced mask + logit store + exp accumulate
        {
            float xs[16];
            const float* xr = xbuf + rr * XST + qq * 16;
            #pragma unroll
            for (int e = 0; e < 4; e++) {
                float4 vv = *(const float4*)(xr + 4 * e);
                xs[4 * e] = vv.x; xs[4 * e + 1] = vv.y; xs[4 * e + 2] = vv.z; xs[4 * e + 3] = vv.w;
            }
            size_t gb = ((size_t)b * L_ + l0 + rr) * L_ + t * 64 + qq * 16;
            if (mode == 0) {
                uint4 mv = *(const uint4*)(maskp + gb);
                uint32_t ws[4] = {mv.x, mv.y, mv.z, mv.w};
                #pragma unroll
                for (int wd = 0; wd < 4; wd++) {
                    if (ws[wd] & 0x000000ffu) xs[4 * wd] = -CUDART_INF_F;
                    if (ws[wd] & 0x0000ff00u) xs[4 * wd + 1] = -CUDART_INF_F;
                    if (ws[wd] & 0x00ff0000u) xs[4 * wd + 2] = -CUDART_INF_F;
                    if (ws[wd] & 0xff000000u) xs[4 * wd + 3] = -CUDART_INF_F;
                }
            } else {
                const uint4* mp = (const uint4*)((const uint32_t*)maskp + gb);
                #pragma unroll
                for (int e = 0; e < 4; e++) {
                    uint4 mv = mp[e];
                    if (mv.x) xs[4 * e] = -CUDART_INF_F;
                    if (mv.y) xs[4 * e + 1] = -CUDART_INF_F;
                    if (mv.z) xs[4 * e + 2] = -CUDART_INF_F;
                    if (mv.w) xs[4 * e + 3] = -CUDART_INF_F;
                }
            }
            #pragma unroll
            for (int e = 0; e < 4; e++)
                *(float4*)(attn + gb + 4 * e) =
                    make_float4(xs[4 * e], xs[4 * e + 1], xs[4 * e + 2], xs[4 * e + 3]);
            #pragma unroll
            for (int j = 0; j < 16; j++) run_s += __expf(xs[j]);
        }
    }

    // ---- merge per-quarter sums -> per-row invS ----
    stp[rr * 4 + qq] = run_s;
    __syncthreads();
    float invS;
    {
        float s = stp[rr * 4 + 0] + stp[rr * 4 + 1] + stp[rr * 4 + 2] + stp[rr * 4 + 3];
        invS = 1.f / s;
    }
    __syncthreads();

    // ================= phase 2: probs + O = P@V (row-domain epilogue) =================
    float accO[8][4] = {};
    for (int t = 0; t < NS; t++) {
        {
            size_t gb = ((size_t)b * L_ + l0 + rr) * L_ + t * 64 + qq * 16;
            float4 pv[4];
            #pragma unroll
            for (int e = 0; e < 4; e++) {
                float4 xv = *(const float4*)(attn + gb + 4 * e);
                pv[e] = make_float4(__expf(xv.x) * invS, __expf(xv.y) * invS,
                                    __expf(xv.z) * invS, __expf(xv.w) * invS);
                *(float4*)(attn + gb + 4 * e) = pv[e];
            }
            st_blk(sm, O_P, rr, 2 * qq, pv[0], pv[1]);
            st_blk(sm, O_P, rr, 2 * qq + 1, pv[2], pv[3]);
        }
        fill_V(t);
        __syncthreads();
        #pragma unroll
        for (int kkx = 0; kkx < 2; kkx++) {
            int kc = 2 * wc + kkx;
            uint32_t Ph[4], Pl[4];
            LDSM4(Ph, adA(O_P, kc, 1));
            LDSM4(Pl, adA(O_P, kc, 0));
            #pragma unroll
            for (int np = 0; np < 4; np++) {
                uint32_t bh[4], bl_[4];
                LDSM4T(bh, adBT(O_K, np, kkx, 1));
                MMA(accO[2 * np], Ph, bh);     MMA(accO[2 * np], Pl, bh);
                MMA(accO[2 * np + 1], Ph, bh + 2); MMA(accO[2 * np + 1], Pl, bh + 2);
                LDSM4T(bl_, adBT(O_K, np, kkx, 0));
                MMA(accO[2 * np], Ph, bl_);    MMA(accO[2 * np + 1], Ph, bl_ + 2);
            }
        }
        __syncthreads();
    }
    // ---- split-k reduction (wc=0 partial -> ring; wc=1 adds and stores) ----
    if (wc == 0) {
        #pragma unroll
        for (int g = 0; g < 8; g++) {
            int j0 = 8 * g + 2 * c2;
            #pragma unroll
            for (int h = 0; h < 2; h++)
                *(float2*)(ring + (r0 + 8 * h) * GS + j0) =
                    make_float2(accO[g][2 * h], accO[g][2 * h + 1]);
        }
    }
    __syncthreads();
    if (wc == 1) {
        #pragma unroll
        for (int g = 0; g < 8; g++) {
            int j0 = 8 * g + 2 * c2;
            #pragma unroll
            for (int h = 0; h < 2; h++) {
                int i = r0 + 8 * h;
                float2 pp = *(const float2*)(ring + i * GS + j0);
                *(float2*)(out + ((size_t)b * L_ + l0 + i) * 64 + j0) =
                    make_float2(accO[g][2 * h] + pp.x, accO[g][2 * h + 1] + pp.y);
            }
        }
    }
}

extern "C" void kernel_launch(void* const* d_in, const int* in_sizes, int n_in,
                              void* d_out, int out_size) {
    const float* q = (const float*)d_in[0];
    const float* k = (const float*)d_in[1];
    const float* v = (const float*)d_in[2];
    const float* pos = (const float*)d_in[3];
    const char* msk = (const char*)d_in[4];
    float* out = (float*)d_out;
    float* attn = out + (size_t)B_ * L_ * 64;

    cudaFuncSetAttribute(fused_mma_kernel,
                         cudaFuncAttributeMaxDynamicSharedMemorySize, SMEMB);
    fused_mma_kernel<<<dim3(16, B_), 256, SMEMB>>>(q, k, v, pos, msk, out, attn);
}

// round 17
// speedup vs baseline: 1.2845x; 1.1486x over previous
#include <cuda_runtime.h>
#include <cuda_bf16.h>
#include <cstdint>
#include <math_constants.h>

#define B_ 64
#define L_ 1024
#define P_ 2047
#define NS 16
#define SBI 272
#define TI  (64 * SBI)
#define GS  72
#define GSZ (64 * GS)

#define O_V  0                  // Q tile during prologue, V tile in main loop
#define O_R  TI
#define O_K  (2 * TI)
#define O_P  (3 * TI)
#define O_G  (4 * TI)           // ring, 2 slots
#define O_ST (O_G + 2 * GSZ * 4)   // stats: 64 rows x 2 wc
#define O_MC (O_ST + 128 * 4)
#define SMEMB (O_MC + 16)       // ~107 KB -> 2 CTAs/SM

__device__ float g_S[B_ * L_];

__device__ __forceinline__ uint32_t smem_u32(const void* p) {
    uint32_t a;
    asm("{ .reg .u64 t; cvta.to.shared.u64 t, %1; cvt.u32.u64 %0, t; }" : "=r"(a) : "l"(p));
    return a;
}
#define LDSM4(r, a) \
    asm volatile("ldmatrix.sync.aligned.m8n8.x4.shared.b16 {%0,%1,%2,%3}, [%4];" \
        : "=r"((r)[0]), "=r"((r)[1]), "=r"((r)[2]), "=r"((r)[3]) : "r"(a))
#define LDSM4T(r, a) \
    asm volatile("ldmatrix.sync.aligned.m8n8.x4.trans.shared.b16 {%0,%1,%2,%3}, [%4];" \
        : "=r"((r)[0]), "=r"((r)[1]), "=r"((r)[2]), "=r"((r)[3]) : "r"(a))
#define MMA(c, a, b) \
    asm volatile("mma.sync.aligned.m16n8k16.row.col.f32.bf16.bf16.f32 " \
        "{%0,%1,%2,%3}, {%4,%5,%6,%7}, {%8,%9}, {%0,%1,%2,%3};" \
        : "+f"((c)[0]), "+f"((c)[1]), "+f"((c)[2]), "+f"((c)[3]) \
        : "r"((a)[0]), "r"((a)[1]), "r"((a)[2]), "r"((a)[3]), "r"((b)[0]), "r"((b)[1]))

__device__ __forceinline__ uint32_t pk2(float a, float b) {
    return (uint32_t)__bfloat16_as_ushort(__float2bfloat16(a)) |
           ((uint32_t)__bfloat16_as_ushort(__float2bfloat16(b)) << 16);
}
__device__ __forceinline__ float bfres(float x) {
    return x - __bfloat162float(__float2bfloat16(x));
}
__device__ __forceinline__ void st_blk(char* sm, int oT, int r, int bl, float4 a, float4 b) {
    uint4 hi = make_uint4(pk2(a.x, a.y), pk2(a.z, a.w), pk2(b.x, b.y), pk2(b.z, b.w));
    uint4 lo = make_uint4(pk2(bfres(a.x), bfres(a.y)), pk2(bfres(a.z), bfres(a.w)),
                          pk2(bfres(b.x), bfres(b.y)), pk2(bfres(b.z), bfres(b.w)));
    char* p = sm + oT + r * SBI + bl * 32;
    *(uint4*)p = hi;
    *(uint4*)(p + 16) = lo;
}

__global__ __launch_bounds__(256, 2)
void fused_fa2_kernel(const float* __restrict__ q, const float* __restrict__ kk,
                      const float* __restrict__ v, const float* __restrict__ pos,
                      const char* __restrict__ maskp, float* __restrict__ out,
                      float* __restrict__ attn) {
    extern __shared__ char sm[];
    const uint32_t sb = smem_u32(sm);
    const int tid = threadIdx.x;
    const int lane = tid & 31, w = tid >> 5;
    const int wr = w & 3, wc = w >> 2;     // 4 warps in m, 2 in n (and k for PV)
    const int b = blockIdx.y, l0 = blockIdx.x * 64;

    const float* qb = q + (size_t)b * L_ * 64;
    const float* kb = kk + (size_t)b * L_ * 64;
    const float* vb = v + (size_t)b * L_ * 64;
    const float* pb = pos + (size_t)b * P_ * 64;

    float* ring = (float*)(sm + O_G);
    float* stp  = (float*)(sm + O_ST);
    int* cnt = (int*)(sm + O_MC);

    // ---- mask dtype detection (first 8KB) ----
    if (tid < 2) cnt[tid] = 0;
    __syncthreads();
    {
        int c0 = 0, c1 = 0;
        #pragma unroll
        for (int e = 0; e < 2; e++) {
            uint4 u = ((const uint4*)maskp)[tid * 2 + e];
            uint32_t ws[4] = {u.x, u.y, u.z, u.w};
            #pragma unroll
            for (int wd = 0; wd < 4; wd++) {
                c0 += ((ws[wd] & 0x000000ffu) != 0);
                c1 += ((ws[wd] & 0x0000ff00u) != 0);
            }
        }
        if (c0) atomicAdd(&cnt[0], c0);
        if (c1) atomicAdd(&cnt[1], c1);
    }

    auto fill_K = [&](int t) {
        #pragma unroll
        for (int e = 0; e < 2; e++) {
            int tt = tid + e * 256, r = tt & 63, bl = tt >> 6;
            const float* ap = kb + (size_t)(t * 64 + r) * 64 + bl * 8;
            st_blk(sm, O_K, r, bl, *(const float4*)ap, *(const float4*)(ap + 4));
        }
    };
    auto fill_V = [&](int t) {
        #pragma unroll
        for (int e = 0; e < 2; e++) {
            int tt = tid + e * 256, r = tt & 63, bl = tt >> 6;
            const float* ap = vb + (size_t)(t * 64 + r) * 64 + bl * 8;
            st_blk(sm, O_V, r, bl, *(const float4*)ap, *(const float4*)(ap + 4));
        }
    };
    auto fill_P = [&](int win) {
        #pragma unroll
        for (int e = 0; e < 2; e++) {
            int tt = tid + e * 256, r = tt & 63, bl = tt >> 6;
            int pr = l0 + 64 * win + r; if (pr > P_ - 1) pr = P_ - 1;
            const float* ap = pb + (size_t)pr * 64 + bl * 8;
            st_blk(sm, O_P, r, bl, *(const float4*)ap, *(const float4*)(ap + 4));
        }
    };

    // prologue: Q -> O_V, R -> O_R (scaled 1/8), K0, P win0
    #pragma unroll
    for (int e = 0; e < 2; e++) {
        int tt = tid + e * 256, r = tt & 63, bl = tt >> 6;
        const float* ap = qb + (size_t)(l0 + r) * 64 + bl * 8;
        float4 a0 = *(const float4*)ap, a1 = *(const float4*)(ap + 4);
        a0.x *= .125f; a0.y *= .125f; a0.z *= .125f; a0.w *= .125f;
        a1.x *= .125f; a1.y *= .125f; a1.z *= .125f; a1.w *= .125f;
        st_blk(sm, O_V, r, bl, a0, a1);
        const float* rp = qb + (size_t)(L_ - 1 - (l0 + r)) * 64 + bl * 8;
        float4 r0v = *(const float4*)rp, r1v = *(const float4*)(rp + 4);
        r0v.x *= .125f; r0v.y *= .125f; r0v.z *= .125f; r0v.w *= .125f;
        r1v.x *= .125f; r1v.y *= .125f; r1v.z *= .125f; r1v.w *= .125f;
        st_blk(sm, O_R, r, bl, r0v, r1v);
    }
    fill_K(0); fill_P(0);
    __syncthreads();
    const int mode = (cnt[0] > 0 && cnt[1] > 0) ? 0 : 1;

    auto adA = [&](int oT, int kc, int hi) -> uint32_t {
        int row = 16 * wr + (lane & 15), blk = 2 * kc + (lane >> 4);
        return sb + oT + row * SBI + blk * 32 + (hi ? 0 : 16);
    };
    auto adB = [&](int oT, int np, int kc, int hi) -> uint32_t {
        int nrow = 32 * wc + 16 * np + 8 * (lane >> 4) + (lane & 7);
        int blk = 2 * kc + ((lane >> 3) & 1);
        return sb + oT + nrow * SBI + blk * 32 + (hi ? 0 : 16);
    };
    auto adBT = [&](int oT, int np, int kc2, int hi) -> uint32_t {
        int krow = 32 * wc + 16 * kc2 + (lane & 15);
        int blk = 2 * np + (lane >> 4);
        return sb + oT + krow * SBI + blk * 32 + (hi ? 0 : 16);
    };
    const int r0 = 16 * wr + (lane >> 2), c2 = lane & 3;

    // persistent Q fragments (O_V slot becomes V buffer afterwards)
    uint32_t Qh[4][4], Ql[4][4];
    #pragma unroll
    for (int kc = 0; kc < 4; kc++) { LDSM4(Qh[kc], adA(O_V, kc, 1)); LDSM4(Ql[kc], adA(O_V, kc, 0)); }

    auto gemm_S = [&](float acc[4][4]) {
        #pragma unroll
        for (int kc = 0; kc < 4; kc++)
            #pragma unroll
            for (int np = 0; np < 2; np++) {
                uint32_t bh[4], bl_[4];
                LDSM4(bh, adB(O_K, np, kc, 1));
                MMA(acc[2 * np], Qh[kc], bh);     MMA(acc[2 * np], Ql[kc], bh);
                MMA(acc[2 * np + 1], Qh[kc], bh + 2); MMA(acc[2 * np + 1], Ql[kc], bh + 2);
                LDSM4(bl_, adB(O_K, np, kc, 0));
                MMA(acc[2 * np], Qh[kc], bl_);    MMA(acc[2 * np + 1], Qh[kc], bl_ + 2);
            }
    };
    auto gemm_G = [&](float acc[4][4]) {
        #pragma unroll
        for (int kc = 0; kc < 4; kc++) {
            uint32_t rh[4], rl[4];
            LDSM4(rh, adA(O_R, kc, 1));
            LDSM4(rl, adA(O_R, kc, 0));
            #pragma unroll
            for (int np = 0; np < 2; np++) {
                uint32_t bh[4], bl_[4];
                LDSM4(bh, adB(O_P, np, kc, 1));
                MMA(acc[2 * np], rh, bh);     MMA(acc[2 * np], rl, bh);
                MMA(acc[2 * np + 1], rh, bh + 2); MMA(acc[2 * np + 1], rl, bh + 2);
                LDSM4(bl_, adB(O_P, np, kc, 0));
                MMA(acc[2 * np], rh, bl_);    MMA(acc[2 * np + 1], rh, bl_ + 2);
            }
        }
    };
    auto ring_store = [&](float acc[4][4], int slot) {
        float* gn = ring + slot * GSZ;
        #pragma unroll
        for (int nf = 0; nf < 4; nf++) {
            int j0 = 32 * wc + 8 * nf + 2 * c2;
            #pragma unroll
            for (int h = 0; h < 2; h++) {
                int i = r0 + 8 * h;
                *(float2*)(gn + i * GS + j0) = make_float2(acc[nf][2 * h], acc[nf][2 * h + 1]);
            }
        }
    };

    // ---- prologue G0 ----
    {
        float accG[4][4] = {};
        gemm_G(accG);
        __syncthreads();
        ring_store(accG, 0);
        fill_P(1);
        __syncthreads();
    }

    float run_s[2] = {0.f, 0.f};
    float accO[8][4] = {};     // split-k partial: this warp's k in [32wc, 32wc+32)

    // ================= fused main loop =================
    for (int t = 0; t < NS; t++) {
        float accS[4][4] = {};
        float accG[4][4] = {};
        gemm_S(accS);
        gemm_G(accG);
        __syncthreads();                           // BAR1
        ring_store(accG, (t + 1) & 1);
        if (t < NS - 1) fill_K(t + 1);
        fill_P(t + 2);
        fill_V(t);
        __syncthreads();                           // BAR2
        // epilogue: bias + mask + logit STG + exp -> p fragments
        const float* gc = ring + (t & 1) * GSZ;
        const float* gn = ring + ((t + 1) & 1) * GSZ;
        uint32_t Ph[2][4], Pl[2][4];
        #pragma unroll
        for (int nf = 0; nf < 4; nf++) {
            int j0 = 32 * wc + 8 * nf + 2 * c2;
            int kcl = nf >> 1;
            #pragma unroll
            for (int h = 0; h < 2; h++) {
                int i = r0 + 8 * h;
                int s0 = i + j0, s1 = s0 + 1;
                float x0 = accS[nf][2 * h] + ((s0 < 64) ? gc : gn)[i * GS + (s0 & 63)];
                float x1 = accS[nf][2 * h + 1] + ((s1 < 64) ? gc : gn)[i * GS + (s1 & 63)];
                size_t gidx = ((size_t)b * L_ + l0 + i) * L_ + t * 64 + j0;
                if (mode == 0) {
                    unsigned short mv = *(const unsigned short*)(maskp + gidx);
                    if (mv & 0x00ff) x0 = -CUDART_INF_F;
                    if (mv & 0xff00) x1 = -CUDART_INF_F;
                } else {
                    uint2 mv = *(const uint2*)((const uint32_t*)maskp + gidx);
                    if (mv.x) x0 = -CUDART_INF_F;
                    if (mv.y) x1 = -CUDART_INF_F;
                }
                *(float2*)(attn + gidx) = make_float2(x0, x1);
                float e0 = __expf(x0), e1 = __expf(x1);
                run_s[h] += e0 + e1;
                int reg = 2 * (nf & 1) + h;
                Ph[kcl][reg] = pk2(e0, e1);
                Pl[kcl][reg] = pk2(bfres(e0), bfres(e1));
            }
        }
        // PV: accO += p(k-half) @ V(t)
        #pragma unroll
        for (int kkx = 0; kkx < 2; kkx++)
            #pragma unroll
            for (int np = 0; np < 4; np++) {
                uint32_t bh[4], bl_[4];
                LDSM4T(bh, adBT(O_V, np, kkx, 1));
                MMA(accO[2 * np], Ph[kkx], bh);     MMA(accO[2 * np], Pl[kkx], bh);
                MMA(accO[2 * np + 1], Ph[kkx], bh + 2); MMA(accO[2 * np + 1], Pl[kkx], bh + 2);
                LDSM4T(bl_, adBT(O_V, np, kkx, 0));
                MMA(accO[2 * np], Ph[kkx], bl_);    MMA(accO[2 * np + 1], Ph[kkx], bl_ + 2);
            }
    }

    // ---- row sums: quad shfl + cross-wc via smem ----
    #pragma unroll
    for (int h = 0; h < 2; h++) {
        float s = run_s[h];
        s += __shfl_xor_sync(0xffffffffu, s, 1);
        s += __shfl_xor_sync(0xffffffffu, s, 2);
        run_s[h] = s;
        if (c2 == 0) stp[(r0 + 8 * h) * 2 + wc] = s;
    }
    __syncthreads();
    float invS[2];
    #pragma unroll
    for (int h = 0; h < 2; h++) {
        int i = r0 + 8 * h;
        float s = stp[i * 2 + 0] + stp[i * 2 + 1];
        invS[h] = 1.f / s;
        if (c2 == 0 && wc == 0) g_S[(size_t)b * L_ + l0 + i] = s;
    }
    __syncthreads();

    // ---- split-k reduction + O store (with invS) ----
    if (wc == 0) {
        #pragma unroll
        for (int g = 0; g < 8; g++) {
            int j0 = 8 * g + 2 * c2;
            #pragma unroll
            for (int h = 0; h < 2; h++)
                *(float2*)(ring + (r0 + 8 * h) * GS + j0) =
                    make_float2(accO[g][2 * h], accO[g][2 * h + 1]);
        }
    }
    __syncthreads();
    if (wc == 1) {
        #pragma unroll
        for (int g = 0; g < 8; g++) {
            int j0 = 8 * g + 2 * c2;
            #pragma unroll
            for (int h = 0; h < 2; h++) {
                int i = r0 + 8 * h;
                float2 pp = *(const float2*)(ring + i * GS + j0);
                *(float2*)(out + ((size_t)b * L_ + l0 + i) * 64 + j0) =
                    make_float2((accO[g][2 * h] + pp.x) * invS[h],
                                (accO[g][2 * h + 1] + pp.y) * invS[h]);
            }
        }
    }
}

// ---- pass 2: logits -> probabilities (exp + normalize), streaming ----
__global__ __launch_bounds__(256)
void norm_kernel(float* __restrict__ attn) {
    int gid = blockIdx.x * 256 + threadIdx.x;
    int row = gid >> 6;
    int seg = gid & 63;
    float invS = 1.f / g_S[row];
    float* p = attn + (size_t)row * L_ + seg * 16;
    #pragma unroll
    for (int e = 0; e < 4; e++) {
        float4 x = *(float4*)(p + 4 * e);
        x.x = __expf(x.x) * invS; x.y = __expf(x.y) * invS;
        x.z = __expf(x.z) * invS; x.w = __expf(x.w) * invS;
        *(float4*)(p + 4 * e) = x;
    }
}

extern "C" void kernel_launch(void* const* d_in, const int* in_sizes, int n_in,
                              void* d_out, int out_size) {
    const float* q = (const float*)d_in[0];
    const float* k = (const float*)d_in[1];
    const float* v = (const float*)d_in[2];
    const float* pos = (const float*)d_in[3];
    const char* msk = (const char*)d_in[4];
    float* out = (float*)d_out;
    float* attn = out + (size_t)B_ * L_ * 64;

    cudaFuncSetAttribute(fused_fa2_kernel,
                         cudaFuncAttributeMaxDynamicSharedMemorySize, SMEMB);
    fused_fa2_kernel<<<dim3(16, B_), 256, SMEMB>>>(q, k, v, pos, msk, out, attn);
    norm_kernel<<<(B_ * L_ * L_) / (256 * 16), 256>>>(attn);
}